// round 4
// baseline (speedup 1.0000x reference)
#include <cuda_runtime.h>

#define D 128
#define MAXN 50000
#define TM 64

// ---------------- scratch (no allocations allowed) ----------------
__device__ float g_agg[MAXN * D];   // aggregation buffer (reused both layers)
__device__ float g_deg[MAXN];       // in-degree (same for both layers)
__device__ float g_h[MAXN * D];     // pre-BN GEMM output
__device__ float g_h1[MAXN * D];    // post BN+ReLU layer-1 output
__device__ float g_stats[4 * D];    // [colsum | colsumsq | scale | shift]

// ---------------- zero scratch ----------------
__global__ void zero_kernel(int zero_deg) {
    int i = blockIdx.x * blockDim.x + threadIdx.x;
    int stride = gridDim.x * blockDim.x;
    float4 z = make_float4(0.f, 0.f, 0.f, 0.f);
    for (int j = i; j < MAXN * D / 4; j += stride) ((float4*)g_agg)[j] = z;
    if (zero_deg) {
        for (int j = i; j < MAXN; j += stride) g_deg[j] = 0.f;
    }
    if (i < 2 * D) g_stats[i] = 0.f;
}

// ---------------- edge scatter: one warp per edge, float4 vector atomics ----------------
// edge_index is int32 on device (JAX default x64-disabled downcasts int64 -> int32).
__global__ void scatter_kernel(const float* __restrict__ xext, int useInternal,
                               const int* __restrict__ ei, int E, int addDeg) {
    const float* feat = useInternal ? g_h1 : xext;
    int gtid = blockIdx.x * blockDim.x + threadIdx.x;
    int warp = gtid >> 5;
    int lane = gtid & 31;
    if (warp >= E) return;
    int s = __ldg(&ei[warp]);      // src
    int d = __ldg(&ei[E + warp]);  // dst
    float4 v = ((const float4*)(feat + (size_t)s * D))[lane];
    float* p = g_agg + (size_t)d * D + lane * 4;
    asm volatile("red.global.add.v4.f32 [%0], {%1,%2,%3,%4};"
                 :: "l"(p), "f"(v.x), "f"(v.y), "f"(v.z), "f"(v.w) : "memory");
    if (addDeg && lane == 0) atomicAdd(&g_deg[d], 1.0f);
}

// ---------------- fused GEMM: h = (agg/deg)@Wl + x@Wr + b, + column stats ----------------
// Tile: 64 rows x 128 cols per block, 256 threads, each thread 8x4 outputs.
__global__ __launch_bounds__(256) void gemm_kernel(
    const float* __restrict__ xext, int useInternal,
    const float* __restrict__ Wl, const float* __restrict__ Wr,
    const float* __restrict__ bias, int M)
{
    const float* xin = useInternal ? g_h1 : xext;
    __shared__ float Ws[32][128];      // K-chunk of W
    __shared__ float As[64][36];       // K-chunk of A (padded row: 36 floats, 16B aligned)
    __shared__ float rscale[64];
    __shared__ float s_sum[D];
    __shared__ float s_sq[D];

    int tid = threadIdx.x;
    int tx = tid & 31;   // cols tx*4 .. tx*4+3
    int ty = tid >> 5;   // rows ty*8 .. ty*8+7
    int row0 = blockIdx.x * TM;

    if (tid < TM) {
        int gr = row0 + tid;
        float dg = (gr < M) ? g_deg[gr] : 1.f;
        rscale[tid] = 1.f / fmaxf(dg, 1.f);
    }
    if (tid < D) { s_sum[tid] = 0.f; s_sq[tid] = 0.f; }

    float acc[8][4];
#pragma unroll
    for (int r = 0; r < 8; r++)
#pragma unroll
        for (int j = 0; j < 4; j++) acc[r][j] = 0.f;

    for (int c = 0; c < 8; c++) {
        int k0 = c * 32;
        const float* Wsrc = (k0 < 128) ? (Wl + k0 * D) : (Wr + (k0 - 128) * D);
        const float* Asrc = (k0 < 128) ? g_agg : xin;
        int koff = k0 & 127;
        int scaleIt = (k0 < 128);
        __syncthreads();
        // load W chunk: 32x128 floats = 1024 float4
#pragma unroll
        for (int i = 0; i < 4; i++) {
            int idx = tid + i * 256;
            int kr = idx >> 5;
            int cc = (idx & 31) * 4;
            *(float4*)&Ws[kr][cc] = *(const float4*)&Wsrc[kr * D + cc];
        }
        // load A chunk: 64x32 floats = 512 float4 (with mean-scale applied on the agg half)
#pragma unroll
        for (int i = 0; i < 2; i++) {
            int idx = tid + i * 256;
            int r = idx >> 3;
            int cc = (idx & 7) * 4;
            int gr = row0 + r;
            float4 v = make_float4(0.f, 0.f, 0.f, 0.f);
            if (gr < M) v = *(const float4*)&Asrc[(size_t)gr * D + koff + cc];
            if (scaleIt) {
                float sf = rscale[r];
                v.x *= sf; v.y *= sf; v.z *= sf; v.w *= sf;
            }
            *(float4*)&As[r][cc] = v;
        }
        __syncthreads();
#pragma unroll
        for (int kk = 0; kk < 32; kk += 4) {
            float4 w0 = *(float4*)&Ws[kk + 0][tx * 4];
            float4 w1 = *(float4*)&Ws[kk + 1][tx * 4];
            float4 w2 = *(float4*)&Ws[kk + 2][tx * 4];
            float4 w3 = *(float4*)&Ws[kk + 3][tx * 4];
#pragma unroll
            for (int r = 0; r < 8; r++) {
                float4 a = *(float4*)&As[ty * 8 + r][kk];
                acc[r][0] += a.x * w0.x; acc[r][1] += a.x * w0.y; acc[r][2] += a.x * w0.z; acc[r][3] += a.x * w0.w;
                acc[r][0] += a.y * w1.x; acc[r][1] += a.y * w1.y; acc[r][2] += a.y * w1.z; acc[r][3] += a.y * w1.w;
                acc[r][0] += a.z * w2.x; acc[r][1] += a.z * w2.y; acc[r][2] += a.z * w2.z; acc[r][3] += a.z * w2.w;
                acc[r][0] += a.w * w3.x; acc[r][1] += a.w * w3.y; acc[r][2] += a.w * w3.z; acc[r][3] += a.w * w3.w;
            }
        }
    }

    // epilogue: +bias, store pre-BN h, accumulate column stats
    float4 bv = ((const float4*)bias)[tx];
    float cs0 = 0, cs1 = 0, cs2 = 0, cs3 = 0;
    float cq0 = 0, cq1 = 0, cq2 = 0, cq3 = 0;
#pragma unroll
    for (int r = 0; r < 8; r++) {
        int gr = row0 + ty * 8 + r;
        if (gr < M) {
            float4 o;
            o.x = acc[r][0] + bv.x;
            o.y = acc[r][1] + bv.y;
            o.z = acc[r][2] + bv.z;
            o.w = acc[r][3] + bv.w;
            *(float4*)&g_h[(size_t)gr * D + tx * 4] = o;
            cs0 += o.x; cs1 += o.y; cs2 += o.z; cs3 += o.w;
            cq0 += o.x * o.x; cq1 += o.y * o.y; cq2 += o.z * o.z; cq3 += o.w * o.w;
        }
    }
    atomicAdd(&s_sum[tx * 4 + 0], cs0); atomicAdd(&s_sum[tx * 4 + 1], cs1);
    atomicAdd(&s_sum[tx * 4 + 2], cs2); atomicAdd(&s_sum[tx * 4 + 3], cs3);
    atomicAdd(&s_sq[tx * 4 + 0], cq0); atomicAdd(&s_sq[tx * 4 + 1], cq1);
    atomicAdd(&s_sq[tx * 4 + 2], cq2); atomicAdd(&s_sq[tx * 4 + 3], cq3);
    __syncthreads();
    if (tid < D) {
        atomicAdd(&g_stats[tid], s_sum[tid]);
        atomicAdd(&g_stats[D + tid], s_sq[tid]);
    }
}

// ---------------- BN params -> scale/shift ----------------
__global__ void stats_kernel(const float* __restrict__ gamma,
                             const float* __restrict__ beta, int M) {
    int c = threadIdx.x;
    float inv = 1.f / (float)M;
    float mean = g_stats[c] * inv;
    float var = g_stats[D + c] * inv - mean * mean;
    float sc = gamma[c] * rsqrtf(var + 1e-5f);
    g_stats[2 * D + c] = sc;
    g_stats[3 * D + c] = beta[c] - mean * sc;
}

// ---------------- apply BN + ReLU (layer 1) ----------------
__global__ void apply_relu_kernel(int M) {
    int i = blockIdx.x * blockDim.x + threadIdx.x;
    if (i >= M * (D / 4)) return;
    int c4 = i & (D / 4 - 1);
    float4 v = ((const float4*)g_h)[i];
    float4 sc = *(const float4*)&g_stats[2 * D + c4 * 4];
    float4 sh = *(const float4*)&g_stats[3 * D + c4 * 4];
    float4 o;
    o.x = fmaxf(fmaf(v.x, sc.x, sh.x), 0.f);
    o.y = fmaxf(fmaf(v.y, sc.y, sh.y), 0.f);
    o.z = fmaxf(fmaf(v.z, sc.z, sh.z), 0.f);
    o.w = fmaxf(fmaf(v.w, sc.w, sh.w), 0.f);
    ((float4*)g_h1)[i] = o;
}

// ---------------- apply BN + residual + ReLU (layer 2) ----------------
__global__ void final_kernel(const float* __restrict__ xin, float* __restrict__ out, int M) {
    int i = blockIdx.x * blockDim.x + threadIdx.x;
    if (i >= M * (D / 4)) return;
    int c4 = i & (D / 4 - 1);
    float4 v = ((const float4*)g_h)[i];
    float4 xv = ((const float4*)xin)[i];
    float4 sc = *(const float4*)&g_stats[2 * D + c4 * 4];
    float4 sh = *(const float4*)&g_stats[3 * D + c4 * 4];
    float4 o;
    o.x = fmaxf(fmaf(v.x, sc.x, sh.x) + xv.x, 0.f);
    o.y = fmaxf(fmaf(v.y, sc.y, sh.y) + xv.y, 0.f);
    o.z = fmaxf(fmaf(v.z, sc.z, sh.z) + xv.z, 0.f);
    o.w = fmaxf(fmaf(v.w, sc.w, sh.w) + xv.w, 0.f);
    ((float4*)out)[i] = o;
}

extern "C" void kernel_launch(void* const* d_in, const int* in_sizes, int n_in,
                              void* d_out, int out_size) {
    const float* x       = (const float*)d_in[0];
    const int*   ei      = (const int*)d_in[1];   // int32 edge_index (JAX x64 disabled)
    const float* W1l     = (const float*)d_in[2];
    const float* b1      = (const float*)d_in[3];
    const float* W1r     = (const float*)d_in[4];
    const float* g1      = (const float*)d_in[5];
    const float* bt1     = (const float*)d_in[6];
    const float* W2l     = (const float*)d_in[7];
    const float* b2      = (const float*)d_in[8];
    const float* W2r     = (const float*)d_in[9];
    const float* g2      = (const float*)d_in[10];
    const float* bt2     = (const float*)d_in[11];
    float* out = (float*)d_out;

    int M = in_sizes[0] / D;
    int E = in_sizes[1] / 2;
    int scatter_blocks = (E + 7) / 8;          // 8 warps (edges) per block
    int gemm_blocks = (M + TM - 1) / TM;
    int ew_blocks = (M * (D / 4) + 255) / 256;

    // ---- layer 1 ----
    zero_kernel<<<1024, 256>>>(1);
    scatter_kernel<<<scatter_blocks, 256>>>(x, 0, ei, E, 1);
    gemm_kernel<<<gemm_blocks, 256>>>(x, 0, W1l, W1r, b1, M);
    stats_kernel<<<1, D>>>(g1, bt1, M);
    apply_relu_kernel<<<ew_blocks, 256>>>(M);

    // ---- layer 2 ----
    zero_kernel<<<1024, 256>>>(0);
    scatter_kernel<<<scatter_blocks, 256>>>(nullptr, 1, ei, E, 0);
    gemm_kernel<<<gemm_blocks, 256>>>(nullptr, 1, W2l, W2r, b2, M);
    stats_kernel<<<1, D>>>(g2, bt2, M);
    final_kernel<<<ew_blocks, 256>>>(x, out, M);
}

// round 7
// speedup vs baseline: 1.2578x; 1.2578x over previous
#include <cuda_runtime.h>
#include <cstdint>

#define D 128
#define MAXN 50000

// ---------------- scratch (no allocations allowed) ----------------
__device__ float g_agg[MAXN * D];   // aggregation buffer (reused both layers)
__device__ float g_deg[MAXN];       // in-degree (same for both layers)
__device__ float g_h[MAXN * D];     // pre-BN GEMM output
__device__ float g_h1[MAXN * D];    // post BN+ReLU layer-1 output
__device__ float g_stats[4 * D];    // [colsum | colsumsq | scale | shift]
__device__ float g_wt[2 * 256 * 128]; // tf32 weights per layer, [layer][k=256][n=128]

__device__ __forceinline__ float to_tf32(float x) {
    uint32_t u;
    asm("cvt.rna.tf32.f32 %0, %1;" : "=r"(u) : "f"(x));
    return __uint_as_float(u);
}

// ---------------- zero scratch ----------------
__global__ void zero_kernel(int zero_deg) {
    int i = blockIdx.x * blockDim.x + threadIdx.x;
    int stride = gridDim.x * blockDim.x;
    float4 z = make_float4(0.f, 0.f, 0.f, 0.f);
    for (int j = i; j < MAXN * D / 4; j += stride) ((float4*)g_agg)[j] = z;
    if (zero_deg) {
        for (int j = i; j < MAXN; j += stride) g_deg[j] = 0.f;
    }
    if (i < 2 * D) g_stats[i] = 0.f;
}

// ---------------- weights -> tf32, [k][n] layout (both layers, once) ----------------
__global__ void wt_kernel(const float* __restrict__ W1l, const float* __restrict__ W1r,
                          const float* __restrict__ W2l, const float* __restrict__ W2r) {
    int i = blockIdx.x * blockDim.x + threadIdx.x;
    if (i >= 256 * 128) return;
    int k = i >> 7;     // 0..255
    int n = i & 127;    // 0..127
    float v1 = (k < 128) ? W1l[k * 128 + n] : W1r[(k - 128) * 128 + n];
    float v2 = (k < 128) ? W2l[k * 128 + n] : W2r[(k - 128) * 128 + n];
    g_wt[i] = to_tf32(v1);
    g_wt[256 * 128 + i] = to_tf32(v2);
}

// ---------------- edge scatter: one warp per edge, float4 vector atomics ----------------
__global__ void scatter_kernel(const float* __restrict__ xext, int useInternal,
                               const int* __restrict__ ei, int E, int addDeg) {
    const float* feat = useInternal ? g_h1 : xext;
    int gtid = blockIdx.x * blockDim.x + threadIdx.x;
    int warp = gtid >> 5;
    int lane = gtid & 31;
    if (warp >= E) return;
    int s = __ldg(&ei[warp]);      // src
    int d = __ldg(&ei[E + warp]);  // dst
    float4 v = ((const float4*)(feat + (size_t)s * D))[lane];
    float* p = g_agg + (size_t)d * D + lane * 4;
    asm volatile("red.global.add.v4.f32 [%0], {%1,%2,%3,%4};"
                 :: "l"(p), "f"(v.x), "f"(v.y), "f"(v.z), "f"(v.w) : "memory");
    if (addDeg && lane == 0) atomicAdd(&g_deg[d], 1.0f);
}

// ---------------- mma.sync tf32 GEMM: h = (agg/deg)@Wl + x@Wr + b ----------------
// CTA: 128 rows x 128 cols. 256 threads = 8 warps (4 along M x 2 along N).
// Warp tile 32x64 = 2 (m16) x 8 (n8) atoms of m16n8k8. K=256 in 8 chunks of 32.
__global__ __launch_bounds__(256) void gemm_mma(
    const float* __restrict__ xext, int useInternal, int layer,
    const float* __restrict__ bias, int M)
{
    const float* xin = useInternal ? g_h1 : xext;
    const float* wt = g_wt + (size_t)layer * (256 * 128);
    __shared__ float As[128][36];   // stride 36: A-frag lds conflict-free (4r+c)
    __shared__ float Bs[32][136];   // stride 136: B-frag lds conflict-free (8k+n)
    __shared__ float rs[128];
    __shared__ float sbias[128];

    int tid = threadIdx.x;
    int lane = tid & 31;
    int wid = tid >> 5;
    int warpM = wid & 3;     // 0..3 -> rows warpM*32
    int warpN = wid >> 2;    // 0..1 -> cols warpN*64
    int row0 = blockIdx.x * 128;

    if (tid < 128) {
        int gr = row0 + tid;
        float dg = (gr < M) ? g_deg[gr] : 1.f;
        rs[tid] = 1.f / fmaxf(dg, 1.f);
        sbias[tid] = bias[tid];
    }

    float acc[2][8][4];
#pragma unroll
    for (int ma = 0; ma < 2; ma++)
#pragma unroll
        for (int na = 0; na < 8; na++)
#pragma unroll
            for (int j = 0; j < 4; j++) acc[ma][na][j] = 0.f;

    for (int c = 0; c < 8; c++) {
        int k0 = c * 32;
        const float* Asrc = (k0 < 128) ? g_agg : xin;
        int koff = k0 & 127;
        int scaleIt = (k0 < 128);
        __syncthreads();
        // A chunk: 128x32 fp32 (scaled, tf32-rounded). 1024 float4, 4/thread.
#pragma unroll
        for (int i = 0; i < 4; i++) {
            int idx = tid + i * 256;
            int r = idx >> 3;
            int cc = (idx & 7) * 4;
            int gr = row0 + r;
            float4 v = make_float4(0.f, 0.f, 0.f, 0.f);
            if (gr < M) {
                v = *(const float4*)&Asrc[(size_t)gr * D + koff + cc];
                if (scaleIt) { float s = rs[r]; v.x *= s; v.y *= s; v.z *= s; v.w *= s; }
            }
            v.x = to_tf32(v.x); v.y = to_tf32(v.y); v.z = to_tf32(v.z); v.w = to_tf32(v.w);
            *(float4*)&As[r][cc] = v;
        }
        // B chunk: 32x128 (already tf32, [k][n]). 1024 float4, 4/thread.
#pragma unroll
        for (int i = 0; i < 4; i++) {
            int idx = tid + i * 256;
            int k = idx >> 5;
            int nn = (idx & 31) * 4;
            *(float4*)&Bs[k][nn] = *(const float4*)&wt[(size_t)(k0 + k) * 128 + nn];
        }
        __syncthreads();
#pragma unroll
        for (int kk = 0; kk < 32; kk += 8) {
            uint32_t a[2][4];
            int ar = warpM * 32 + (lane >> 2);
            int ac = kk + (lane & 3);
#pragma unroll
            for (int ma = 0; ma < 2; ma++) {
                int r = ar + ma * 16;
                a[ma][0] = __float_as_uint(As[r][ac]);
                a[ma][1] = __float_as_uint(As[r + 8][ac]);
                a[ma][2] = __float_as_uint(As[r][ac + 4]);
                a[ma][3] = __float_as_uint(As[r + 8][ac + 4]);
            }
#pragma unroll
            for (int na = 0; na < 8; na++) {
                int bn = warpN * 64 + na * 8 + (lane >> 2);
                int bk = kk + (lane & 3);
                uint32_t b0 = __float_as_uint(Bs[bk][bn]);
                uint32_t b1 = __float_as_uint(Bs[bk + 4][bn]);
#pragma unroll
                for (int ma = 0; ma < 2; ma++) {
                    asm volatile(
                        "mma.sync.aligned.m16n8k8.row.col.f32.tf32.tf32.f32 "
                        "{%0,%1,%2,%3}, {%4,%5,%6,%7}, {%8,%9}, {%0,%1,%2,%3};"
                        : "+f"(acc[ma][na][0]), "+f"(acc[ma][na][1]),
                          "+f"(acc[ma][na][2]), "+f"(acc[ma][na][3])
                        : "r"(a[ma][0]), "r"(a[ma][1]), "r"(a[ma][2]), "r"(a[ma][3]),
                          "r"(b0), "r"(b1));
                }
            }
        }
    }

    // epilogue: +bias, store h. C layout: rows lane>>2 (+8), cols 2*(lane&3)(+1).
    int r0 = row0 + warpM * 32 + (lane >> 2);
    int c0 = warpN * 64 + 2 * (lane & 3);
#pragma unroll
    for (int ma = 0; ma < 2; ma++) {
        int gr = r0 + ma * 16;
#pragma unroll
        for (int na = 0; na < 8; na++) {
            int col = c0 + na * 8;
            if (gr < M) {
                float2 o = make_float2(acc[ma][na][0] + sbias[col],
                                       acc[ma][na][1] + sbias[col + 1]);
                *(float2*)&g_h[(size_t)gr * D + col] = o;
            }
            if (gr + 8 < M) {
                float2 o = make_float2(acc[ma][na][2] + sbias[col],
                                       acc[ma][na][3] + sbias[col + 1]);
                *(float2*)&g_h[(size_t)(gr + 8) * D + col] = o;
            }
        }
    }
}

// ---------------- column stats over g_h -> g_stats[0..2D) ----------------
__global__ void colstats_kernel(int M) {
    __shared__ float ss[D], sq[D];
    int tid = threadIdx.x;
    int tx = tid & 31;
    int ty = tid >> 5;
    if (tid < D) { ss[tid] = 0.f; sq[tid] = 0.f; }
    __syncthreads();
    int row0 = blockIdx.x * 256;
    float4 s = make_float4(0.f, 0.f, 0.f, 0.f);
    float4 q = make_float4(0.f, 0.f, 0.f, 0.f);
    for (int r = ty; r < 256; r += 8) {
        int gr = row0 + r;
        if (gr >= M) break;
        float4 v = *(const float4*)&g_h[(size_t)gr * D + tx * 4];
        s.x += v.x; s.y += v.y; s.z += v.z; s.w += v.w;
        q.x += v.x * v.x; q.y += v.y * v.y; q.z += v.z * v.z; q.w += v.w * v.w;
    }
    atomicAdd(&ss[tx * 4 + 0], s.x); atomicAdd(&ss[tx * 4 + 1], s.y);
    atomicAdd(&ss[tx * 4 + 2], s.z); atomicAdd(&ss[tx * 4 + 3], s.w);
    atomicAdd(&sq[tx * 4 + 0], q.x); atomicAdd(&sq[tx * 4 + 1], q.y);
    atomicAdd(&sq[tx * 4 + 2], q.z); atomicAdd(&sq[tx * 4 + 3], q.w);
    __syncthreads();
    if (tid < D) {
        atomicAdd(&g_stats[tid], ss[tid]);
        atomicAdd(&g_stats[D + tid], sq[tid]);
    }
}

// ---------------- BN params -> scale/shift ----------------
__global__ void stats_kernel(const float* __restrict__ gamma,
                             const float* __restrict__ beta, int M) {
    int c = threadIdx.x;
    float inv = 1.f / (float)M;
    float mean = g_stats[c] * inv;
    float var = g_stats[D + c] * inv - mean * mean;
    float sc = gamma[c] * rsqrtf(var + 1e-5f);
    g_stats[2 * D + c] = sc;
    g_stats[3 * D + c] = beta[c] - mean * sc;
}

// ---------------- apply BN + ReLU (layer 1) ----------------
__global__ void apply_relu_kernel(int M) {
    int i = blockIdx.x * blockDim.x + threadIdx.x;
    if (i >= M * (D / 4)) return;
    int c4 = i & (D / 4 - 1);
    float4 v = ((const float4*)g_h)[i];
    float4 sc = *(const float4*)&g_stats[2 * D + c4 * 4];
    float4 sh = *(const float4*)&g_stats[3 * D + c4 * 4];
    float4 o;
    o.x = fmaxf(fmaf(v.x, sc.x, sh.x), 0.f);
    o.y = fmaxf(fmaf(v.y, sc.y, sh.y), 0.f);
    o.z = fmaxf(fmaf(v.z, sc.z, sh.z), 0.f);
    o.w = fmaxf(fmaf(v.w, sc.w, sh.w), 0.f);
    ((float4*)g_h1)[i] = o;
}

// ---------------- apply BN + residual + ReLU (layer 2) ----------------
__global__ void final_kernel(const float* __restrict__ xin, float* __restrict__ out, int M) {
    int i = blockIdx.x * blockDim.x + threadIdx.x;
    if (i >= M * (D / 4)) return;
    int c4 = i & (D / 4 - 1);
    float4 v = ((const float4*)g_h)[i];
    float4 xv = ((const float4*)xin)[i];
    float4 sc = *(const float4*)&g_stats[2 * D + c4 * 4];
    float4 sh = *(const float4*)&g_stats[3 * D + c4 * 4];
    float4 o;
    o.x = fmaxf(fmaf(v.x, sc.x, sh.x) + xv.x, 0.f);
    o.y = fmaxf(fmaf(v.y, sc.y, sh.y) + xv.y, 0.f);
    o.z = fmaxf(fmaf(v.z, sc.z, sh.z) + xv.z, 0.f);
    o.w = fmaxf(fmaf(v.w, sc.w, sh.w) + xv.w, 0.f);
    ((float4*)out)[i] = o;
}

extern "C" void kernel_launch(void* const* d_in, const int* in_sizes, int n_in,
                              void* d_out, int out_size) {
    const float* x       = (const float*)d_in[0];
    const int*   ei      = (const int*)d_in[1];   // int32 edge_index (JAX x64 disabled)
    const float* W1l     = (const float*)d_in[2];
    const float* b1      = (const float*)d_in[3];
    const float* W1r     = (const float*)d_in[4];
    const float* g1      = (const float*)d_in[5];
    const float* bt1     = (const float*)d_in[6];
    const float* W2l     = (const float*)d_in[7];
    const float* b2      = (const float*)d_in[8];
    const float* W2r     = (const float*)d_in[9];
    const float* g2      = (const float*)d_in[10];
    const float* bt2     = (const float*)d_in[11];
    float* out = (float*)d_out;

    int M = in_sizes[0] / D;
    int E = in_sizes[1] / 2;
    int scatter_blocks = (E + 7) / 8;
    int gemm_blocks = (M + 127) / 128;
    int ew_blocks = (M * (D / 4) + 255) / 256;
    int cs_blocks = (M + 255) / 256;

    // weights: tf32 convert once (used by both layers)
    wt_kernel<<<128, 256>>>(W1l, W1r, W2l, W2r);

    // ---- layer 1 ----
    zero_kernel<<<1024, 256>>>(1);
    scatter_kernel<<<scatter_blocks, 256>>>(x, 0, ei, E, 1);
    gemm_mma<<<gemm_blocks, 256>>>(x, 0, 0, b1, M);
    colstats_kernel<<<cs_blocks, 256>>>(M);
    stats_kernel<<<1, D>>>(g1, bt1, M);
    apply_relu_kernel<<<ew_blocks, 256>>>(M);

    // ---- layer 2 ----
    zero_kernel<<<1024, 256>>>(0);
    scatter_kernel<<<scatter_blocks, 256>>>(nullptr, 1, ei, E, 0);
    gemm_mma<<<gemm_blocks, 256>>>(nullptr, 1, 1, b2, M);
    colstats_kernel<<<cs_blocks, 256>>>(M);
    stats_kernel<<<1, D>>>(g2, bt2, M);
    final_kernel<<<ew_blocks, 256>>>(x, out, M);
}